// round 1
// baseline (speedup 1.0000x reference)
#include <cuda_runtime.h>
#include <math.h>

// Problem constants
constexpr int HD = 1024;   // hidden dim
constexpr int NH = 8;      // heads
constexpr int DH = 128;    // head dim
constexpr int BB = 4;      // batch
constexpr int TT = 2048;   // seq len
constexpr int MM = BB * TT; // 8192 rows

typedef unsigned long long ull;

// ---- scratch (allocation-free: __device__ globals) ----
__device__ float g_xn[MM * HD];
__device__ float g_q[MM * HD];   // [B, NH, T, DH]
__device__ float g_k[MM * HD];
__device__ float g_v[MM * HD];
__device__ float g_attn[MM * HD]; // [B, T, HD]

// ---- f32x2 helpers (packed fp32 pipe: 2 FMA per issue slot) ----
__device__ __forceinline__ void fma2(ull &d, ull a, ull b) {
    asm("fma.rn.f32x2 %0, %1, %2, %0;" : "+l"(d) : "l"(a), "l"(b));
}
__device__ __forceinline__ void mul2(ull &d, ull a) {
    asm("mul.rn.f32x2 %0, %1, %0;" : "+l"(d) : "l"(a));
}
__device__ __forceinline__ ull fpack(float a, float b) {
    ull r;
    asm("mov.b64 %0, {%1, %2};" : "=l"(r) : "r"(__float_as_uint(a)), "r"(__float_as_uint(b)));
    return r;
}
__device__ __forceinline__ float f2lo(ull u) { return __uint_as_float((unsigned)u); }
__device__ __forceinline__ float f2hi(ull u) { return __uint_as_float((unsigned)(u >> 32)); }

// ============================================================
// LayerNorm: one block per row of 1024
// ============================================================
__global__ void __launch_bounds__(256) ln_kernel(
    const float* __restrict__ x, const float* __restrict__ gamma,
    const float* __restrict__ beta, float* __restrict__ xn)
{
    int row = blockIdx.x;
    int tid = threadIdx.x;
    const float* xr = x + (size_t)row * HD;
    float4 v = *(const float4*)&xr[tid * 4];
    float s  = v.x + v.y + v.z + v.w;
    float ss = v.x * v.x + v.y * v.y + v.z * v.z + v.w * v.w;
    #pragma unroll
    for (int o = 16; o; o >>= 1) {
        s  += __shfl_xor_sync(0xffffffffu, s,  o);
        ss += __shfl_xor_sync(0xffffffffu, ss, o);
    }
    __shared__ float rs[8], rss[8];
    if ((tid & 31) == 0) { rs[tid >> 5] = s; rss[tid >> 5] = ss; }
    __syncthreads();
    s = 0.f; ss = 0.f;
    #pragma unroll
    for (int i = 0; i < 8; i++) { s += rs[i]; ss += rss[i]; }
    float mu  = s * (1.0f / HD);
    float inv = rsqrtf(ss * (1.0f / HD) - mu * mu + 1e-5f);
    float4 g  = *(const float4*)&gamma[tid * 4];
    float4 be = *(const float4*)&beta[tid * 4];
    float4 o;
    o.x = (v.x - mu) * inv * g.x + be.x;
    o.y = (v.y - mu) * inv * g.y + be.y;
    o.z = (v.z - mu) * inv * g.z + be.z;
    o.w = (v.w - mu) * inv * g.w + be.w;
    *(float4*)&xn[(size_t)row * HD + tid * 4] = o;
}

// ============================================================
// SGEMM NT: C[m,n] = sum_k A[m,k] * W[n,k]
// M=8192, N=1024, K=1024. Tiles 128x128x16, 8x8 per thread, f32x2.
// LAYOUT 0: head-split output [B, NH, T, DH]
// LAYOUT 1: row-major + residual add
// ============================================================
template<int LAYOUT>
__global__ void __launch_bounds__(256) sgemm_nt(
    const float* __restrict__ A, const float* __restrict__ W,
    float* __restrict__ C, const float* __restrict__ R)
{
    const int Kd = 1024;
    __shared__ float As[16][128];
    __shared__ float Bs[16][128];
    int tid = threadIdx.x;
    int tx = tid & 15, ty = tid >> 4;
    int m0 = blockIdx.y << 7, n0 = blockIdx.x << 7;

    ull acc[8][4];
    #pragma unroll
    for (int i = 0; i < 8; i++)
        #pragma unroll
        for (int j = 0; j < 4; j++) acc[i][j] = 0ull;

    for (int k0 = 0; k0 < Kd; k0 += 16) {
        #pragma unroll
        for (int i = 0; i < 2; i++) {
            int vv = tid + (i << 8);
            int row = vv >> 2, kc = (vv & 3) << 2;
            float4 a = *(const float4*)&A[(size_t)(m0 + row) * Kd + k0 + kc];
            As[kc + 0][row] = a.x; As[kc + 1][row] = a.y;
            As[kc + 2][row] = a.z; As[kc + 3][row] = a.w;
            float4 b = *(const float4*)&W[(size_t)(n0 + row) * Kd + k0 + kc];
            Bs[kc + 0][row] = b.x; Bs[kc + 1][row] = b.y;
            Bs[kc + 2][row] = b.z; Bs[kc + 3][row] = b.w;
        }
        __syncthreads();
        #pragma unroll
        for (int k = 0; k < 16; k++) {
            float4 a0 = *(const float4*)&As[k][ty << 3];
            float4 a1 = *(const float4*)&As[k][(ty << 3) + 4];
            float ar[8] = {a0.x, a0.y, a0.z, a0.w, a1.x, a1.y, a1.z, a1.w};
            ull br[4];
            #pragma unroll
            for (int j = 0; j < 4; j++)
                br[j] = *(const ull*)&Bs[k][(tx << 3) + (j << 1)];
            #pragma unroll
            for (int i = 0; i < 8; i++) {
                ull ad = fpack(ar[i], ar[i]);
                #pragma unroll
                for (int j = 0; j < 4; j++) fma2(acc[i][j], ad, br[j]);
            }
        }
        __syncthreads();
    }

    #pragma unroll
    for (int i = 0; i < 8; i++) {
        int m = m0 + (ty << 3) + i;
        #pragma unroll
        for (int j = 0; j < 4; j++) {
            int n = n0 + (tx << 3) + (j << 1);
            float c0 = f2lo(acc[i][j]), c1 = f2hi(acc[i][j]);
            if (LAYOUT == 0) {
                int b = m >> 11, t = m & 2047;
                int h = n >> 7, d = n & 127;
                size_t base = (((size_t)(b * NH + h)) * TT + t) * DH + d;
                C[base]     = c0;
                C[base + 1] = c1;
            } else {
                size_t idx = (size_t)m * HD + n;
                C[idx]     = c0 + R[idx];
                C[idx + 1] = c1 + R[idx + 1];
            }
        }
    }
}

// ============================================================
// Flash attention: causal, BM=BN=64, D=128, online softmax.
// Thread tile: S rows ty*4+i, cols tx+16j; O rows ty*4+i, cols tx*8..+7.
// Q/K row-major in smem (pitch 134) so d-pairs are natural LDS.64
// operands for fma.rn.f32x2 (no pack instructions in the S loop).
// ============================================================
constexpr int QK_PITCH = 134;
constexpr int FLASH_SMEM_FLOATS = 64 * QK_PITCH * 2 + 64 * 128 + 64 * 65 + 64 + 64 + 256 + 256;
constexpr int FLASH_SMEM = FLASH_SMEM_FLOATS * 4;

__global__ void __launch_bounds__(256) flash_kernel(
    const float* __restrict__ Qg, const float* __restrict__ Kg,
    const float* __restrict__ Vg, float* __restrict__ Og)
{
    extern __shared__ float smf[];
    float* Qs    = smf;                    // [64][134]
    float* Ks    = Qs + 64 * QK_PITCH;     // [64][134]
    float* Vs    = Ks + 64 * QK_PITCH;     // [64][128]
    float* Ss    = Vs + 64 * 128;          // [64][65]
    float* m_sh  = Ss + 64 * 65;           // [64]
    float* a_sh  = m_sh + 64;              // [64]
    float* pmax  = a_sh + 64;              // [256]
    float* lpart = pmax + 256;             // [256]

    int tid = threadIdx.x;
    int tx = tid & 15, ty = tid >> 4;
    int qb = blockIdx.x, bh = blockIdx.y;
    int q0 = qb << 6;
    const float scale = 0.08838834764831845f; // 1/sqrt(128)
    const float* qp = Qg + (size_t)bh * TT * DH;
    const float* kp = Kg + (size_t)bh * TT * DH;
    const float* vp = Vg + (size_t)bh * TT * DH;

    // load Q tile (pre-scaled), row-major
    #pragma unroll
    for (int i = 0; i < 8; i++) {
        int vv = tid + (i << 8);
        int row = vv >> 5, c4 = (vv & 31) << 2;
        float4 a = *(const float4*)&qp[(size_t)(q0 + row) * DH + c4];
        float* d = &Qs[row * QK_PITCH + c4];
        d[0] = a.x * scale; d[1] = a.y * scale;
        d[2] = a.z * scale; d[3] = a.w * scale;
    }
    if (tid < 64) m_sh[tid] = -1e30f;

    int sr = tid & 63, sq = tid >> 6;  // softmax thread mapping: 4 threads/row
    float lp = 0.f;                     // per-thread partial row sum

    ull o2[4][4];
    #pragma unroll
    for (int i = 0; i < 4; i++)
        #pragma unroll
        for (int j = 0; j < 4; j++) o2[i][j] = 0ull;

    for (int kb = 0; kb <= qb; kb++) {
        __syncthreads(); // prev-iter consumers done before overwriting Ks/Vs/Ss
        int kk0 = kb << 6;
        #pragma unroll
        for (int i = 0; i < 8; i++) {
            int vv = tid + (i << 8);
            int row = vv >> 5, c4 = (vv & 31) << 2;
            float4 a = *(const float4*)&kp[(size_t)(kk0 + row) * DH + c4];
            float* d = &Ks[row * QK_PITCH + c4];
            d[0] = a.x; d[1] = a.y; d[2] = a.z; d[3] = a.w;
            *(float4*)&Vs[vv << 2] = *(const float4*)&vp[(size_t)kk0 * DH + (vv << 2)];
        }
        __syncthreads();

        // S = Q K^T via f32x2 over d-pairs
        ull s2[4][4];
        #pragma unroll
        for (int i = 0; i < 4; i++)
            #pragma unroll
            for (int j = 0; j < 4; j++) s2[i][j] = 0ull;
        #pragma unroll 4
        for (int dp = 0; dp < 128; dp += 2) {
            ull qr[4], kr[4];
            #pragma unroll
            for (int i = 0; i < 4; i++)
                qr[i] = *(const ull*)&Qs[(ty * 4 + i) * QK_PITCH + dp];
            #pragma unroll
            for (int j = 0; j < 4; j++)
                kr[j] = *(const ull*)&Ks[(tx + (j << 4)) * QK_PITCH + dp];
            #pragma unroll
            for (int i = 0; i < 4; i++)
                #pragma unroll
                for (int j = 0; j < 4; j++) fma2(s2[i][j], qr[i], kr[j]);
        }
        // causal mask + write S to shared
        #pragma unroll
        for (int i = 0; i < 4; i++) {
            int rg = q0 + ty * 4 + i;
            #pragma unroll
            for (int j = 0; j < 4; j++) {
                int cg = kk0 + tx + (j << 4);
                float s = f2lo(s2[i][j]) + f2hi(s2[i][j]);
                Ss[(ty * 4 + i) * 65 + tx + (j << 4)] = (cg <= rg) ? s : -1e30f;
            }
        }
        __syncthreads();

        // partial row max (4 threads per row, 16 cols each)
        {
            float mx = -1e30f;
            const float* p = &Ss[sr * 65 + sq * 16];
            #pragma unroll
            for (int c = 0; c < 16; c++) mx = fmaxf(mx, p[c]);
            pmax[tid] = mx;
        }
        __syncthreads();
        if (tid < 64) {
            float mo = m_sh[tid];
            float mx = fmaxf(fmaxf(pmax[tid], pmax[tid + 64]),
                             fmaxf(pmax[tid + 128], pmax[tid + 192]));
            mx = fmaxf(mx, mo);
            m_sh[tid] = mx;
            a_sh[tid] = __expf(mo - mx);
        }
        __syncthreads();
        // exp + partial sums, P written in place
        {
            float mx = m_sh[sr];
            float al = a_sh[sr];
            float* p = &Ss[sr * 65 + sq * 16];
            float sum = 0.f;
            #pragma unroll
            for (int c = 0; c < 16; c++) {
                float e = __expf(p[c] - mx);
                p[c] = e;
                sum += e;
            }
            lp = lp * al + sum;
        }
        __syncthreads();

        // rescale O, accumulate P @ V (f32x2, V pairs contiguous)
        #pragma unroll
        for (int i = 0; i < 4; i++) {
            float al = a_sh[ty * 4 + i];
            ull ad = fpack(al, al);
            #pragma unroll
            for (int j = 0; j < 4; j++) mul2(o2[i][j], ad);
        }
        #pragma unroll 2
        for (int n = 0; n < 64; n++) {
            ull va[4];
            #pragma unroll
            for (int j = 0; j < 4; j++)
                va[j] = *(const ull*)&Vs[(n << 7) + (tx << 3) + (j << 1)];
            #pragma unroll
            for (int i = 0; i < 4; i++) {
                float p = Ss[(ty * 4 + i) * 65 + n];
                ull pd = fpack(p, p);
                #pragma unroll
                for (int j = 0; j < 4; j++) fma2(o2[i][j], pd, va[j]);
            }
        }
    }

    lpart[tid] = lp;
    __syncthreads();
    int h = bh & 7, b = bh >> 3;
    #pragma unroll
    for (int i = 0; i < 4; i++) {
        int r = ty * 4 + i;
        float l = lpart[r] + lpart[r + 64] + lpart[r + 128] + lpart[r + 192];
        float inv = 1.f / l;
        float* op = Og + (size_t)(b * TT + q0 + r) * HD + (h << 7) + (tx << 3);
        #pragma unroll
        for (int j = 0; j < 4; j++) {
            op[2 * j]     = f2lo(o2[i][j]) * inv;
            op[2 * j + 1] = f2hi(o2[i][j]) * inv;
        }
    }
}

// ============================================================
// Launch
// ============================================================
extern "C" void kernel_launch(void* const* d_in, const int* in_sizes, int n_in,
                              void* d_out, int out_size)
{
    const float* x     = (const float*)d_in[0];
    const float* gamma = (const float*)d_in[1];
    const float* beta  = (const float*)d_in[2];
    const float* Wq    = (const float*)d_in[3];
    const float* Wk    = (const float*)d_in[4];
    const float* Wv    = (const float*)d_in[5];
    const float* Wo    = (const float*)d_in[6];
    float* out = (float*)d_out;

    float *xn, *q, *k, *v, *attn;
    cudaGetSymbolAddress((void**)&xn,   g_xn);
    cudaGetSymbolAddress((void**)&q,    g_q);
    cudaGetSymbolAddress((void**)&k,    g_k);
    cudaGetSymbolAddress((void**)&v,    g_v);
    cudaGetSymbolAddress((void**)&attn, g_attn);

    ln_kernel<<<MM, 256>>>(x, gamma, beta, xn);

    dim3 gg(HD / 128, MM / 128);
    sgemm_nt<0><<<gg, 256>>>(xn, Wq, q, nullptr);
    sgemm_nt<0><<<gg, 256>>>(xn, Wk, k, nullptr);
    sgemm_nt<0><<<gg, 256>>>(xn, Wv, v, nullptr);

    cudaFuncSetAttribute(flash_kernel, cudaFuncAttributeMaxDynamicSharedMemorySize, FLASH_SMEM);
    flash_kernel<<<dim3(TT / 64, BB * NH), 256, FLASH_SMEM>>>(q, k, v, attn);

    sgemm_nt<1><<<gg, 256>>>(attn, Wo, out, x);
}

// round 3
// speedup vs baseline: 1.4536x; 1.4536x over previous
#include <cuda_runtime.h>
#include <cuda_bf16.h>
#include <math.h>
#include <cstdint>

// Problem constants
constexpr int HD = 1024;
constexpr int NH = 8;
constexpr int DH = 128;
constexpr int BB = 4;
constexpr int TT = 2048;
constexpr int MM = BB * TT; // 8192

typedef unsigned long long ull;

// ---- scratch (allocation-free: __device__ globals) ----
__device__ __nv_bfloat16 g_xn2[MM * 2048];        // LN out, [hi | lo] per row
__device__ __nv_bfloat16 g_w2[4][1024 * 2048];    // Wq,Wk,Wv,Wo split [hi | lo]
__device__ float g_q[MM * HD];                    // [B, NH, T, DH]
__device__ float g_k[MM * HD];
__device__ float g_v[MM * HD];
__device__ float g_attn[MM * HD];                 // [B, T, HD]
__device__ __nv_bfloat16 g_attn2[MM * 2048];      // attn split [hi | lo]

// ============================================================
// helpers
// ============================================================
__device__ __forceinline__ uint32_t s2u(const void* p) {
    uint32_t a;
    asm("{ .reg .u64 t; cvta.to.shared.u64 t, %1; cvt.u32.u64 %0, t; }" : "=r"(a) : "l"(p));
    return a;
}
__device__ __forceinline__ void cpasync16(uint32_t smem, const void* g) {
    asm volatile("cp.async.cg.shared.global [%0], [%1], 16;" :: "r"(smem), "l"(g));
}
__device__ __forceinline__ void cpcommit() { asm volatile("cp.async.commit_group;" ::: "memory"); }
template<int N> __device__ __forceinline__ void cpwait() {
    asm volatile("cp.async.wait_group %0;" :: "n"(N) : "memory");
}
__device__ __forceinline__ void ldsm4(uint32_t* r, uint32_t addr) {
    asm volatile("ldmatrix.sync.aligned.m8n8.x4.shared.b16 {%0,%1,%2,%3}, [%4];"
                 : "=r"(r[0]), "=r"(r[1]), "=r"(r[2]), "=r"(r[3]) : "r"(addr));
}
__device__ __forceinline__ void mma16816(float* d, const uint32_t* a, uint32_t b0, uint32_t b1) {
    asm volatile("mma.sync.aligned.m16n8k16.row.col.f32.bf16.bf16.f32 "
                 "{%0,%1,%2,%3}, {%4,%5,%6,%7}, {%8,%9}, {%0,%1,%2,%3};"
                 : "+f"(d[0]), "+f"(d[1]), "+f"(d[2]), "+f"(d[3])
                 : "r"(a[0]), "r"(a[1]), "r"(a[2]), "r"(a[3]), "r"(b0), "r"(b1));
}

// f32x2 helpers (flash kernel)
__device__ __forceinline__ void fma2(ull &d, ull a, ull b) {
    asm("fma.rn.f32x2 %0, %1, %2, %0;" : "+l"(d) : "l"(a), "l"(b));
}
__device__ __forceinline__ void mul2(ull &d, ull a) {
    asm("mul.rn.f32x2 %0, %1, %0;" : "+l"(d) : "l"(a));
}
__device__ __forceinline__ ull fpack(float a, float b) {
    ull r;
    asm("mov.b64 %0, {%1, %2};" : "=l"(r) : "r"(__float_as_uint(a)), "r"(__float_as_uint(b)));
    return r;
}
__device__ __forceinline__ float f2lo(ull u) { return __uint_as_float((unsigned)u); }
__device__ __forceinline__ float f2hi(ull u) { return __uint_as_float((unsigned)(u >> 32)); }

__device__ __forceinline__ void split_bf16(float x, __nv_bfloat16 &h, __nv_bfloat16 &l) {
    h = __float2bfloat16_rn(x);
    l = __float2bfloat16_rn(x - __bfloat162float(h));
}

// ============================================================
// LayerNorm -> bf16 hi/lo split [row][2048]
// ============================================================
__global__ void __launch_bounds__(256) ln_kernel(
    const float* __restrict__ x, const float* __restrict__ gamma,
    const float* __restrict__ beta, __nv_bfloat16* __restrict__ xn2)
{
    int row = blockIdx.x;
    int tid = threadIdx.x;
    const float* xr = x + (size_t)row * HD;
    float4 v = *(const float4*)&xr[tid * 4];
    float s  = v.x + v.y + v.z + v.w;
    float ss = v.x * v.x + v.y * v.y + v.z * v.z + v.w * v.w;
    #pragma unroll
    for (int o = 16; o; o >>= 1) {
        s  += __shfl_xor_sync(0xffffffffu, s,  o);
        ss += __shfl_xor_sync(0xffffffffu, ss, o);
    }
    __shared__ float rs[8], rss[8];
    if ((tid & 31) == 0) { rs[tid >> 5] = s; rss[tid >> 5] = ss; }
    __syncthreads();
    s = 0.f; ss = 0.f;
    #pragma unroll
    for (int i = 0; i < 8; i++) { s += rs[i]; ss += rss[i]; }
    float mu  = s * (1.0f / HD);
    float inv = rsqrtf(ss * (1.0f / HD) - mu * mu + 1e-5f);
    float4 g  = *(const float4*)&gamma[tid * 4];
    float4 be = *(const float4*)&beta[tid * 4];
    float o[4];
    o[0] = (v.x - mu) * inv * g.x + be.x;
    o[1] = (v.y - mu) * inv * g.y + be.y;
    o[2] = (v.z - mu) * inv * g.z + be.z;
    o[3] = (v.w - mu) * inv * g.w + be.w;
    __nv_bfloat16 hi[4], lo[4];
    #pragma unroll
    for (int i = 0; i < 4; i++) split_bf16(o[i], hi[i], lo[i]);
    *(ull*)&xn2[(size_t)row * 2048 + tid * 4]        = *(ull*)hi;
    *(ull*)&xn2[(size_t)row * 2048 + 1024 + tid * 4] = *(ull*)lo;
}

// ============================================================
// fp32 -> bf16 hi/lo split (rows of 1024 -> 2048)
// ============================================================
__global__ void __launch_bounds__(256) conv_split(
    const float* __restrict__ A, __nv_bfloat16* __restrict__ A2)
{
    int i = blockIdx.x * 256 + threadIdx.x;
    float4 v = ((const float4*)A)[i];
    int row = (i * 4) >> 10, col = (i * 4) & 1023;
    __nv_bfloat16 hi[4], lo[4];
    split_bf16(v.x, hi[0], lo[0]);
    split_bf16(v.y, hi[1], lo[1]);
    split_bf16(v.z, hi[2], lo[2]);
    split_bf16(v.w, hi[3], lo[3]);
    *(ull*)&A2[(size_t)row * 2048 + col]        = *(ull*)hi;
    *(ull*)&A2[(size_t)row * 2048 + 1024 + col] = *(ull*)lo;
}

// ============================================================
// mma.sync bf16 GEMM, tripled-K hi/lo split.
// C[m,n] = sum_k A[m,k]*W[n,k]; fp32 accum in registers.
// A2: [8192][2048] (hi|lo), B2: [1024][2048] (hi|lo). Logical K'=3072,
// chunk mapping A:[hi,hi,lo], B:[hi,lo,hi].
// CTA 128x128, 8 warps (4m x 2n), warp tile 32x64, K-chunk 32, 3-stage cp.async.
// smem pitch 80B -> ldmatrix conflict-free (granule stride 5 mod 8).
// ============================================================
constexpr int GPITCH = 80;                   // bytes per 32-bf16 row
constexpr int MAT_STAGE = 128 * GPITCH;      // 10240 B (A or B)
constexpr int STAGE_BYTES = 2 * MAT_STAGE;   // 20480
constexpr int GSTG = 3;
constexpr int GEMM_SMEM = GSTG * STAGE_BYTES;
constexpr int NCHUNK = 96;                   // 3072 / 32

__device__ __forceinline__ void gemm_load_chunk(
    const __nv_bfloat16* __restrict__ A2, const __nv_bfloat16* __restrict__ B2,
    int m0, int n0, int c, uint32_t sbase, int tid)
{
    int s = c % GSTG;
    int kc = c * 32;
    int asrc = (kc >= 2048) ? (kc - 1024) : (kc & 1023);
    int bsrc = (kc >= 2048) ? (kc - 2048) : kc;
    uint32_t aSt = sbase + s * STAGE_BYTES;
    uint32_t bSt = aSt + MAT_STAGE;
    // 128 rows x 4 chunks of 16B each matrix; 256 threads -> 2 each
    #pragma unroll
    for (int p = 0; p < 2; p++) {
        int e = tid + (p << 8);
        int r = e >> 2, cc = e & 3;
        cpasync16(aSt + r * GPITCH + cc * 16, A2 + (size_t)(m0 + r) * 2048 + asrc + cc * 8);
        cpasync16(bSt + r * GPITCH + cc * 16, B2 + (size_t)(n0 + r) * 2048 + bsrc + cc * 8);
    }
    cpcommit();
}

template<int LAYOUT>
__global__ void __launch_bounds__(256, 2) gemm_mma(
    const __nv_bfloat16* __restrict__ A2, const __nv_bfloat16* __restrict__ B2,
    float* __restrict__ C, const float* __restrict__ R)
{
    extern __shared__ char sm[];
    uint32_t sbase = s2u(sm);
    int tid = threadIdx.x;
    int lane = tid & 31, warp = tid >> 5;
    int wm = warp >> 1, wn = warp & 1;          // 4 x 2 warp grid
    int m0 = blockIdx.y << 7, n0 = blockIdx.x << 7;

    float d[2][8][4];
    #pragma unroll
    for (int i = 0; i < 2; i++)
        #pragma unroll
        for (int j = 0; j < 8; j++)
            #pragma unroll
            for (int q = 0; q < 4; q++) d[i][j][q] = 0.f;

    gemm_load_chunk(A2, B2, m0, n0, 0, sbase, tid);
    gemm_load_chunk(A2, B2, m0, n0, 1, sbase, tid);

    // ldmatrix row/col offsets for this lane
    int lr = lane & 15;            // row within 16
    int lk = (lane >> 4) << 3;     // k offset 0/8

    for (int c = 0; c < NCHUNK; c++) {
        cpwait<1>();
        __syncthreads();
        if (c + 2 < NCHUNK) gemm_load_chunk(A2, B2, m0, n0, c + 2, sbase, tid);
        else cpcommit();

        uint32_t aSt = sbase + (c % GSTG) * STAGE_BYTES;
        uint32_t bSt = aSt + MAT_STAGE;
        #pragma unroll
        for (int k16 = 0; k16 < 2; k16++) {
            uint32_t a[2][4], b[4][4];
            #pragma unroll
            for (int mt = 0; mt < 2; mt++)
                ldsm4(a[mt], aSt + (wm * 32 + mt * 16 + lr) * GPITCH + (k16 * 16 + lk) * 2);
            #pragma unroll
            for (int nt = 0; nt < 4; nt++)
                ldsm4(b[nt], bSt + (wn * 64 + nt * 16 + lr) * GPITCH + (k16 * 16 + lk) * 2);
            #pragma unroll
            for (int mt = 0; mt < 2; mt++)
                #pragma unroll
                for (int n8 = 0; n8 < 8; n8++) {
                    int nt = n8 >> 1, odd = n8 & 1;
                    mma16816(d[mt][n8], a[mt], b[nt][odd], b[nt][odd + 2]);
                }
        }
        __syncthreads();
    }

    // epilogue: d0,d1 -> (m, n..n+1); d2,d3 -> (m+8, n..n+1)
    int mb = m0 + wm * 32 + (lane >> 2);
    int nb = n0 + wn * 64 + (lane & 3) * 2;
    #pragma unroll
    for (int mt = 0; mt < 2; mt++) {
        #pragma unroll
        for (int n8 = 0; n8 < 8; n8++) {
            int n = nb + n8 * 8;
            #pragma unroll
            for (int half = 0; half < 2; half++) {
                int m = mb + mt * 16 + half * 8;
                float c0 = d[mt][n8][half * 2], c1 = d[mt][n8][half * 2 + 1];
                if (LAYOUT == 0) {
                    int bI = m >> 11, t = m & 2047;
                    int h = n >> 7, dd = n & 127;
                    float* op = C + (((size_t)(bI * NH + h) * TT + t) * DH) + dd;
                    *(float2*)op = make_float2(c0, c1);
                } else {
                    size_t idx = (size_t)m * HD + n;
                    float2 rr = *(const float2*)&R[idx];
                    *(float2*)&C[idx] = make_float2(c0 + rr.x, c1 + rr.y);
                }
            }
        }
    }
}

// ============================================================
// Flash attention (R1 version): causal, BM=BN=64, f32x2 SIMT
// ============================================================
constexpr int QK_PITCH = 134;
constexpr int FLASH_SMEM_FLOATS = 64 * QK_PITCH * 2 + 64 * 128 + 64 * 65 + 64 + 64 + 256 + 256;
constexpr int FLASH_SMEM = FLASH_SMEM_FLOATS * 4;

__global__ void __launch_bounds__(256) flash_kernel(
    const float* __restrict__ Qg, const float* __restrict__ Kg,
    const float* __restrict__ Vg, float* __restrict__ Og)
{
    extern __shared__ float smf[];
    float* Qs    = smf;
    float* Ks    = Qs + 64 * QK_PITCH;
    float* Vs    = Ks + 64 * QK_PITCH;
    float* Ss    = Vs + 64 * 128;
    float* m_sh  = Ss + 64 * 65;
    float* a_sh  = m_sh + 64;
    float* pmax  = a_sh + 64;
    float* lpart = pmax + 256;

    int tid = threadIdx.x;
    int tx = tid & 15, ty = tid >> 4;
    int qb = blockIdx.x, bh = blockIdx.y;
    int q0 = qb << 6;
    const float scale = 0.08838834764831845f;
    const float* qp = Qg + (size_t)bh * TT * DH;
    const float* kp = Kg + (size_t)bh * TT * DH;
    const float* vp = Vg + (size_t)bh * TT * DH;

    #pragma unroll
    for (int i = 0; i < 8; i++) {
        int vv = tid + (i << 8);
        int row = vv >> 5, c4 = (vv & 31) << 2;
        float4 a = *(const float4*)&qp[(size_t)(q0 + row) * DH + c4];
        float* d = &Qs[row * QK_PITCH + c4];
        d[0] = a.x * scale; d[1] = a.y * scale;
        d[2] = a.z * scale; d[3] = a.w * scale;
    }
    if (tid < 64) m_sh[tid] = -1e30f;

    int sr = tid & 63, sq = tid >> 6;
    float lp = 0.f;

    ull o2[4][4];
    #pragma unroll
    for (int i = 0; i < 4; i++)
        #pragma unroll
        for (int j = 0; j < 4; j++) o2[i][j] = 0ull;

    for (int kb = 0; kb <= qb; kb++) {
        __syncthreads();
        int kk0 = kb << 6;
        #pragma unroll
        for (int i = 0; i < 8; i++) {
            int vv = tid + (i << 8);
            int row = vv >> 5, c4 = (vv & 31) << 2;
            float4 a = *(const float4*)&kp[(size_t)(kk0 + row) * DH + c4];
            float* d = &Ks[row * QK_PITCH + c4];
            d[0] = a.x; d[1] = a.y; d[2] = a.z; d[3] = a.w;
            *(float4*)&Vs[vv << 2] = *(const float4*)&vp[(size_t)kk0 * DH + (vv << 2)];
        }
        __syncthreads();

        ull s2[4][4];
        #pragma unroll
        for (int i = 0; i < 4; i++)
            #pragma unroll
            for (int j = 0; j < 4; j++) s2[i][j] = 0ull;
        #pragma unroll 4
        for (int dp = 0; dp < 128; dp += 2) {
            ull qr[4], kr[4];
            #pragma unroll
            for (int i = 0; i < 4; i++)
                qr[i] = *(const ull*)&Qs[(ty * 4 + i) * QK_PITCH + dp];
            #pragma unroll
            for (int j = 0; j < 4; j++)
                kr[j] = *(const ull*)&Ks[(tx + (j << 4)) * QK_PITCH + dp];
            #pragma unroll
            for (int i = 0; i < 4; i++)
                #pragma unroll
                for (int j = 0; j < 4; j++) fma2(s2[i][j], qr[i], kr[j]);
        }
        #pragma unroll
        for (int i = 0; i < 4; i++) {
            int rg = q0 + ty * 4 + i;
            #pragma unroll
            for (int j = 0; j < 4; j++) {
                int cg = kk0 + tx + (j << 4);
                float s = f2lo(s2[i][j]) + f2hi(s2[i][j]);
                Ss[(ty * 4 + i) * 65 + tx + (j << 4)] = (cg <= rg) ? s : -1e30f;
            }
        }
        __syncthreads();

        {
            float mx = -1e30f;
            const float* p = &Ss[sr * 65 + sq * 16];
            #pragma unroll
            for (int c = 0; c < 16; c++) mx = fmaxf(mx, p[c]);
            pmax[tid] = mx;
        }
        __syncthreads();
        if (tid < 64) {
            float mo = m_sh[tid];
            float mx = fmaxf(fmaxf(pmax[tid], pmax[tid + 64]),
                             fmaxf(pmax[tid + 128], pmax[tid + 192]));
            mx = fmaxf(mx, mo);
            m_sh[tid] = mx;
            a_sh[tid] = __expf(mo - mx);
        }
        __syncthreads();
        {
            float mx = m_sh[sr];
            float al = a_sh[sr];
            float* p = &Ss[sr * 65 + sq * 16];
            float sum = 0.f;
            #pragma unroll
            for (int c = 0; c < 16; c++) {
                float e = __expf(p[c] - mx);
                p[c] = e;
                sum += e;
            }
            lp = lp * al + sum;
        }
        __syncthreads();

        #pragma unroll
        for (int i = 0; i < 4; i++) {
            float al = a_sh[ty * 4 + i];
            ull ad = fpack(al, al);
            #pragma unroll
            for (int j = 0; j < 4; j++) mul2(o2[i][j], ad);
        }
        #pragma unroll 2
        for (int n = 0; n < 64; n++) {
            ull va[4];
            #pragma unroll
            for (int j = 0; j < 4; j++)
                va[j] = *(const ull*)&Vs[(n << 7) + (tx << 3) + (j << 1)];
            #pragma unroll
            for (int i = 0; i < 4; i++) {
                float p = Ss[(ty * 4 + i) * 65 + n];
                ull pd = fpack(p, p);
                #pragma unroll
                for (int j = 0; j < 4; j++) fma2(o2[i][j], pd, va[j]);
            }
        }
    }

    lpart[tid] = lp;
    __syncthreads();
    int h = bh & 7, b = bh >> 3;
    #pragma unroll
    for (int i = 0; i < 4; i++) {
        int r = ty * 4 + i;
        float l = lpart[r] + lpart[r + 64] + lpart[r + 128] + lpart[r + 192];
        float inv = 1.f / l;
        float* op = Og + (size_t)(b * TT + q0 + r) * HD + (h << 7) + (tx << 3);
        #pragma unroll
        for (int j = 0; j < 4; j++) {
            op[2 * j]     = f2lo(o2[i][j]) * inv;
            op[2 * j + 1] = f2hi(o2[i][j]) * inv;
        }
    }
}

// ============================================================
// Launch
// ============================================================
extern "C" void kernel_launch(void* const* d_in, const int* in_sizes, int n_in,
                              void* d_out, int out_size)
{
    const float* x     = (const float*)d_in[0];
    const float* gamma = (const float*)d_in[1];
    const float* beta  = (const float*)d_in[2];
    const float* Wq    = (const float*)d_in[3];
    const float* Wk    = (const float*)d_in[4];
    const float* Wv    = (const float*)d_in[5];
    const float* Wo    = (const float*)d_in[6];
    float* out = (float*)d_out;

    __nv_bfloat16 *xn2, *w2, *attn2;
    float *q, *k, *v, *attn;
    cudaGetSymbolAddress((void**)&xn2,   g_xn2);
    cudaGetSymbolAddress((void**)&w2,    g_w2);
    cudaGetSymbolAddress((void**)&q,     g_q);
    cudaGetSymbolAddress((void**)&k,     g_k);
    cudaGetSymbolAddress((void**)&v,     g_v);
    cudaGetSymbolAddress((void**)&attn,  g_attn);
    cudaGetSymbolAddress((void**)&attn2, g_attn2);

    cudaFuncSetAttribute(gemm_mma<0>, cudaFuncAttributeMaxDynamicSharedMemorySize, GEMM_SMEM);
    cudaFuncSetAttribute(gemm_mma<1>, cudaFuncAttributeMaxDynamicSharedMemorySize, GEMM_SMEM);
    cudaFuncSetAttribute(flash_kernel, cudaFuncAttributeMaxDynamicSharedMemorySize, FLASH_SMEM);

    ln_kernel<<<MM, 256>>>(x, gamma, beta, xn2);

    conv_split<<<1024, 256>>>(Wq, w2 + (size_t)0 * 1024 * 2048);
    conv_split<<<1024, 256>>>(Wk, w2 + (size_t)1 * 1024 * 2048);
    conv_split<<<1024, 256>>>(Wv, w2 + (size_t)2 * 1024 * 2048);
    conv_split<<<1024, 256>>>(Wo, w2 + (size_t)3 * 1024 * 2048);

    dim3 gg(HD / 128, MM / 128);   // (8, 64)
    gemm_mma<0><<<gg, 256, GEMM_SMEM>>>(xn2, w2 + (size_t)0 * 1024 * 2048, q, nullptr);
    gemm_mma<0><<<gg, 256, GEMM_SMEM>>>(xn2, w2 + (size_t)1 * 1024 * 2048, k, nullptr);
    gemm_mma<0><<<gg, 256, GEMM_SMEM>>>(xn2, w2 + (size_t)2 * 1024 * 2048, v, nullptr);

    flash_kernel<<<dim3(TT / 64, BB * NH), 256, FLASH_SMEM>>>(q, k, v, attn);

    conv_split<<<MM, 256>>>(attn, attn2);

    gemm_mma<1><<<gg, 256, GEMM_SMEM>>>(attn2, w2 + (size_t)3 * 1024 * 2048, out, x);
}

// round 4
// speedup vs baseline: 2.3522x; 1.6182x over previous
#include <cuda_runtime.h>
#include <cuda_bf16.h>
#include <math.h>
#include <cstdint>

constexpr int HD = 1024;
constexpr int NH = 8;
constexpr int DH = 128;
constexpr int BB = 4;
constexpr int TT = 2048;
constexpr int MM = BB * TT; // 8192

typedef unsigned long long ull;

// ---- scratch (allocation-free) ----
__device__ __nv_bfloat16 g_xn2[MM * 2048];           // LN out [hi|lo]
__device__ __nv_bfloat16 g_w2[4][1024 * 2048];       // weights split [hi|lo]
__device__ __nv_bfloat16 g_q2[32 * TT * 256];        // [B*NH][T][hi128|lo128], pre-scaled
__device__ __nv_bfloat16 g_k2[32 * TT * 256];
__device__ __nv_bfloat16 g_v2[32 * TT * 256];
__device__ __nv_bfloat16 g_attn2[MM * 2048];         // attn split [hi|lo]

// ============================================================
// helpers
// ============================================================
__device__ __forceinline__ uint32_t s2u(const void* p) {
    uint32_t a;
    asm("{ .reg .u64 t; cvta.to.shared.u64 t, %1; cvt.u32.u64 %0, t; }" : "=r"(a) : "l"(p));
    return a;
}
__device__ __forceinline__ void cpasync16(uint32_t smem, const void* g) {
    asm volatile("cp.async.cg.shared.global [%0], [%1], 16;" :: "r"(smem), "l"(g));
}
__device__ __forceinline__ void cpcommit() { asm volatile("cp.async.commit_group;" ::: "memory"); }
template<int N> __device__ __forceinline__ void cpwait() {
    asm volatile("cp.async.wait_group %0;" :: "n"(N) : "memory");
}
__device__ __forceinline__ void ldsm4(uint32_t* r, uint32_t addr) {
    asm volatile("ldmatrix.sync.aligned.m8n8.x4.shared.b16 {%0,%1,%2,%3}, [%4];"
                 : "=r"(r[0]), "=r"(r[1]), "=r"(r[2]), "=r"(r[3]) : "r"(addr));
}
__device__ __forceinline__ void ldsm4t(uint32_t* r, uint32_t addr) {
    asm volatile("ldmatrix.sync.aligned.m8n8.x4.trans.shared.b16 {%0,%1,%2,%3}, [%4];"
                 : "=r"(r[0]), "=r"(r[1]), "=r"(r[2]), "=r"(r[3]) : "r"(addr));
}
__device__ __forceinline__ void mma16816(float* d, const uint32_t* a, uint32_t b0, uint32_t b1) {
    asm volatile("mma.sync.aligned.m16n8k16.row.col.f32.bf16.bf16.f32 "
                 "{%0,%1,%2,%3}, {%4,%5,%6,%7}, {%8,%9}, {%0,%1,%2,%3};"
                 : "+f"(d[0]), "+f"(d[1]), "+f"(d[2]), "+f"(d[3])
                 : "r"(a[0]), "r"(a[1]), "r"(a[2]), "r"(a[3]), "r"(b0), "r"(b1));
}
__device__ __forceinline__ void split_bf16(float x, __nv_bfloat16 &h, __nv_bfloat16 &l) {
    h = __float2bfloat16_rn(x);
    l = __float2bfloat16_rn(x - __bfloat162float(h));
}
__device__ __forceinline__ uint32_t pack_split_hi(float a, float b) {
    __nv_bfloat16 ha, la, hb, lb;
    split_bf16(a, ha, la); split_bf16(b, hb, lb);
    return (uint32_t)__bfloat16_as_ushort(ha) | ((uint32_t)__bfloat16_as_ushort(hb) << 16);
}
__device__ __forceinline__ void pack_split2(float a, float b, uint32_t &hi, uint32_t &lo) {
    __nv_bfloat16 ha, la, hb, lb;
    split_bf16(a, ha, la); split_bf16(b, hb, lb);
    hi = (uint32_t)__bfloat16_as_ushort(ha) | ((uint32_t)__bfloat16_as_ushort(hb) << 16);
    lo = (uint32_t)__bfloat16_as_ushort(la) | ((uint32_t)__bfloat16_as_ushort(lb) << 16);
}

// ============================================================
// LayerNorm -> bf16 hi/lo split [row][2048]
// ============================================================
__global__ void __launch_bounds__(256) ln_kernel(
    const float* __restrict__ x, const float* __restrict__ gamma,
    const float* __restrict__ beta, __nv_bfloat16* __restrict__ xn2)
{
    int row = blockIdx.x;
    int tid = threadIdx.x;
    const float* xr = x + (size_t)row * HD;
    float4 v = *(const float4*)&xr[tid * 4];
    float s  = v.x + v.y + v.z + v.w;
    float ss = v.x * v.x + v.y * v.y + v.z * v.z + v.w * v.w;
    #pragma unroll
    for (int o = 16; o; o >>= 1) {
        s  += __shfl_xor_sync(0xffffffffu, s,  o);
        ss += __shfl_xor_sync(0xffffffffu, ss, o);
    }
    __shared__ float rs[8], rss[8];
    if ((tid & 31) == 0) { rs[tid >> 5] = s; rss[tid >> 5] = ss; }
    __syncthreads();
    s = 0.f; ss = 0.f;
    #pragma unroll
    for (int i = 0; i < 8; i++) { s += rs[i]; ss += rss[i]; }
    float mu  = s * (1.0f / HD);
    float inv = rsqrtf(ss * (1.0f / HD) - mu * mu + 1e-5f);
    float4 g  = *(const float4*)&gamma[tid * 4];
    float4 be = *(const float4*)&beta[tid * 4];
    float o[4];
    o[0] = (v.x - mu) * inv * g.x + be.x;
    o[1] = (v.y - mu) * inv * g.y + be.y;
    o[2] = (v.z - mu) * inv * g.z + be.z;
    o[3] = (v.w - mu) * inv * g.w + be.w;
    __nv_bfloat16 hi[4], lo[4];
    #pragma unroll
    for (int i = 0; i < 4; i++) split_bf16(o[i], hi[i], lo[i]);
    *(ull*)&xn2[(size_t)row * 2048 + tid * 4]        = *(ull*)hi;
    *(ull*)&xn2[(size_t)row * 2048 + 1024 + tid * 4] = *(ull*)lo;
}

// fp32 -> bf16 hi/lo split (weights)
__global__ void __launch_bounds__(256) conv_split(
    const float* __restrict__ A, __nv_bfloat16* __restrict__ A2)
{
    int i = blockIdx.x * 256 + threadIdx.x;
    float4 v = ((const float4*)A)[i];
    int row = (i * 4) >> 10, col = (i * 4) & 1023;
    __nv_bfloat16 hi[4], lo[4];
    split_bf16(v.x, hi[0], lo[0]);
    split_bf16(v.y, hi[1], lo[1]);
    split_bf16(v.z, hi[2], lo[2]);
    split_bf16(v.w, hi[3], lo[3]);
    *(ull*)&A2[(size_t)row * 2048 + col]        = *(ull*)hi;
    *(ull*)&A2[(size_t)row * 2048 + 1024 + col] = *(ull*)lo;
}

// ============================================================
// mma.sync bf16 GEMM, tripled-K hi/lo split (as R3).
// ============================================================
constexpr int GPITCH = 80;
constexpr int MAT_STAGE = 128 * GPITCH;
constexpr int STAGE_BYTES = 2 * MAT_STAGE;
constexpr int GSTG = 3;
constexpr int GEMM_SMEM = GSTG * STAGE_BYTES;
constexpr int NCHUNK = 96;

__device__ __forceinline__ void gemm_load_chunk(
    const __nv_bfloat16* __restrict__ A2, const __nv_bfloat16* __restrict__ B2,
    int m0, int n0, int c, uint32_t sbase, int tid)
{
    int s = c % GSTG;
    int kc = c * 32;
    int asrc = (kc >= 2048) ? (kc - 1024) : (kc & 1023);
    int bsrc = (kc >= 2048) ? (kc - 2048) : kc;
    uint32_t aSt = sbase + s * STAGE_BYTES;
    uint32_t bSt = aSt + MAT_STAGE;
    #pragma unroll
    for (int p = 0; p < 2; p++) {
        int e = tid + (p << 8);
        int r = e >> 2, cc = e & 3;
        cpasync16(aSt + r * GPITCH + cc * 16, A2 + (size_t)(m0 + r) * 2048 + asrc + cc * 8);
        cpasync16(bSt + r * GPITCH + cc * 16, B2 + (size_t)(n0 + r) * 2048 + bsrc + cc * 8);
    }
    cpcommit();
}

// mainloop shared by both epilogue variants
__device__ __forceinline__ void gemm_core(
    const __nv_bfloat16* A2, const __nv_bfloat16* B2,
    int m0, int n0, uint32_t sbase, int tid, int lane, int wm, int wn,
    float d[2][8][4])
{
    gemm_load_chunk(A2, B2, m0, n0, 0, sbase, tid);
    gemm_load_chunk(A2, B2, m0, n0, 1, sbase, tid);
    int lr = lane & 15;
    int lk = (lane >> 4) << 3;
    for (int c = 0; c < NCHUNK; c++) {
        cpwait<1>();
        __syncthreads();
        if (c + 2 < NCHUNK) gemm_load_chunk(A2, B2, m0, n0, c + 2, sbase, tid);
        else cpcommit();
        uint32_t aSt = sbase + (c % GSTG) * STAGE_BYTES;
        uint32_t bSt = aSt + MAT_STAGE;
        #pragma unroll
        for (int k16 = 0; k16 < 2; k16++) {
            uint32_t a[2][4], b[4][4];
            #pragma unroll
            for (int mt = 0; mt < 2; mt++)
                ldsm4(a[mt], aSt + (wm * 32 + mt * 16 + lr) * GPITCH + (k16 * 16 + lk) * 2);
            #pragma unroll
            for (int nt = 0; nt < 4; nt++)
                ldsm4(b[nt], bSt + (wn * 64 + nt * 16 + lr) * GPITCH + (k16 * 16 + lk) * 2);
            #pragma unroll
            for (int mt = 0; mt < 2; mt++)
                #pragma unroll
                for (int n8 = 0; n8 < 8; n8++) {
                    int nt = n8 >> 1, odd = n8 & 1;
                    mma16816(d[mt][n8], a[mt], b[nt][odd], b[nt][odd + 2]);
                }
        }
        __syncthreads();
    }
}

// QKV variant: writes split bf16 [B,NH,T,256] with scale folded in
__global__ void __launch_bounds__(256, 2) gemm_mma_qkv(
    const __nv_bfloat16* __restrict__ A2, const __nv_bfloat16* __restrict__ B2,
    __nv_bfloat16* __restrict__ Csplit, float scale)
{
    extern __shared__ char sm[];
    uint32_t sbase = s2u(sm);
    int tid = threadIdx.x, lane = tid & 31, warp = tid >> 5;
    int wm = warp >> 1, wn = warp & 1;
    int m0 = blockIdx.y << 7, n0 = blockIdx.x << 7;

    float d[2][8][4];
    #pragma unroll
    for (int i = 0; i < 2; i++)
        #pragma unroll
        for (int j = 0; j < 8; j++)
            #pragma unroll
            for (int q = 0; q < 4; q++) d[i][j][q] = 0.f;

    gemm_core(A2, B2, m0, n0, sbase, tid, lane, wm, wn, d);

    int mb = m0 + wm * 32 + (lane >> 2);
    int nb = n0 + wn * 64 + (lane & 3) * 2;
    #pragma unroll
    for (int mt = 0; mt < 2; mt++) {
        #pragma unroll
        for (int n8 = 0; n8 < 8; n8++) {
            int n = nb + n8 * 8;
            #pragma unroll
            for (int half = 0; half < 2; half++) {
                int m = mb + mt * 16 + half * 8;
                float c0 = d[mt][n8][half * 2] * scale, c1 = d[mt][n8][half * 2 + 1] * scale;
                int bI = m >> 11, t = m & 2047;
                int h = n >> 7, dd = n & 127;
                size_t base = ((size_t)(bI * NH + h) * TT + t) * 256 + dd;
                uint32_t hp, lp;
                pack_split2(c0, c1, hp, lp);
                *(uint32_t*)&Csplit[base]       = hp;
                *(uint32_t*)&Csplit[base + 128] = lp;
            }
        }
    }
}

// Output-projection variant: fp32 + residual
__global__ void __launch_bounds__(256, 2) gemm_mma_out(
    const __nv_bfloat16* __restrict__ A2, const __nv_bfloat16* __restrict__ B2,
    float* __restrict__ C, const float* __restrict__ R)
{
    extern __shared__ char sm[];
    uint32_t sbase = s2u(sm);
    int tid = threadIdx.x, lane = tid & 31, warp = tid >> 5;
    int wm = warp >> 1, wn = warp & 1;
    int m0 = blockIdx.y << 7, n0 = blockIdx.x << 7;

    float d[2][8][4];
    #pragma unroll
    for (int i = 0; i < 2; i++)
        #pragma unroll
        for (int j = 0; j < 8; j++)
            #pragma unroll
            for (int q = 0; q < 4; q++) d[i][j][q] = 0.f;

    gemm_core(A2, B2, m0, n0, sbase, tid, lane, wm, wn, d);

    int mb = m0 + wm * 32 + (lane >> 2);
    int nb = n0 + wn * 64 + (lane & 3) * 2;
    #pragma unroll
    for (int mt = 0; mt < 2; mt++) {
        #pragma unroll
        for (int n8 = 0; n8 < 8; n8++) {
            int n = nb + n8 * 8;
            #pragma unroll
            for (int half = 0; half < 2; half++) {
                int m = mb + mt * 16 + half * 8;
                size_t idx = (size_t)m * HD + n;
                float2 rr = *(const float2*)&R[idx];
                *(float2*)&C[idx] = make_float2(d[mt][n8][half * 2] + rr.x,
                                                d[mt][n8][half * 2 + 1] + rr.y);
            }
        }
    }
}

// ============================================================
// Flash attention on mma.sync, 3-term bf16 split, base-2 softmax.
// BM=BN=64, 8 warps (4m x 2n). Q pre-scaled by scale*log2(e).
// ============================================================
constexpr int FPB = 528;     // Q/K/V smem row pitch bytes (264 bf16)
constexpr int PPB = 144;     // P smem row pitch bytes (72 bf16)
constexpr int FL_Q  = 0;
constexpr int FL_K  = FL_Q + 64 * FPB;
constexpr int FL_V  = FL_K + 2 * 64 * FPB;
constexpr int FL_PH = FL_V + 2 * 64 * FPB;
constexpr int FL_PL = FL_PH + 64 * PPB;
constexpr int FL_PM = FL_PL + 64 * PPB;      // float pmax[2][64]
constexpr int FL_LS = FL_PM + 512;           // float lsum[2][64]
constexpr int FLASH_SMEM = FL_LS + 512;      // 188928 B

__global__ void __launch_bounds__(256, 1) flash_mma(
    const __nv_bfloat16* __restrict__ Q2, const __nv_bfloat16* __restrict__ K2,
    const __nv_bfloat16* __restrict__ V2, __nv_bfloat16* __restrict__ A2out)
{
    extern __shared__ char sm[];
    uint32_t sb = s2u(sm);
    int tid = threadIdx.x, lane = tid & 31, warp = tid >> 5;
    int wm = warp >> 1, wn = warp & 1;
    int qb = blockIdx.x, bh = blockIdx.y;
    int q0 = qb << 6;
    const __nv_bfloat16* qp = Q2 + (size_t)bh * TT * 256;
    const __nv_bfloat16* kp = K2 + (size_t)bh * TT * 256;
    const __nv_bfloat16* vp = V2 + (size_t)bh * TT * 256;
    float* pmaxS = (float*)(sm + FL_PM);
    float* lsumS = (float*)(sm + FL_LS);

    // prologue: Q tile + K/V block 0 in group 0
    #pragma unroll
    for (int p = 0; p < 8; p++) {
        int e = tid + (p << 8);
        int r = e >> 5, c = e & 31;
        cpasync16(sb + FL_Q + r * FPB + c * 16, qp + (size_t)(q0 + r) * 256 + c * 8);
        cpasync16(sb + FL_K + r * FPB + c * 16, kp + (size_t)r * 256 + c * 8);
        cpasync16(sb + FL_V + r * FPB + c * 16, vp + (size_t)r * 256 + c * 8);
    }
    cpcommit();

    float o[8][4];
    #pragma unroll
    for (int i = 0; i < 8; i++)
        #pragma unroll
        for (int j = 0; j < 4; j++) o[i][j] = 0.f;
    float m0r = -1e30f, m1r = -1e30f, l0r = 0.f, l1r = 0.f;

    int lr = lane & 15;
    int lk = (lane >> 4) << 3;
    int r0 = lane >> 2;                 // 0..7
    int rowA = wm * 16 + r0;            // rows rowA, rowA+8

    for (int kb = 0; kb <= qb; kb++) {
        int buf = kb & 1;
        __syncthreads();     // prior reads of buf^1 / P buffers complete
        if (kb < qb) {
            int kn0 = (kb + 1) << 6;
            uint32_t kD = sb + FL_K + (buf ^ 1) * 64 * FPB;
            uint32_t vD = sb + FL_V + (buf ^ 1) * 64 * FPB;
            #pragma unroll
            for (int p = 0; p < 8; p++) {
                int e = tid + (p << 8);
                int r = e >> 5, c = e & 31;
                cpasync16(kD + r * FPB + c * 16, kp + (size_t)(kn0 + r) * 256 + c * 8);
                cpasync16(vD + r * FPB + c * 16, vp + (size_t)(kn0 + r) * 256 + c * 8);
            }
        }
        cpcommit();
        cpwait<1>();
        __syncthreads();

        uint32_t qB = sb + FL_Q;
        uint32_t kB = sb + FL_K + buf * 64 * FPB;
        uint32_t vB = sb + FL_V + buf * 64 * FPB;

        // ---- S = Q K^T, 3-term ----
        float s[4][4];
        #pragma unroll
        for (int i = 0; i < 4; i++)
            #pragma unroll
            for (int j = 0; j < 4; j++) s[i][j] = 0.f;
        #pragma unroll
        for (int term = 0; term < 3; term++) {
            int ac = (term == 2) ? 128 : 0;
            int bc = (term == 1) ? 128 : 0;
            #pragma unroll
            for (int k16 = 0; k16 < 8; k16++) {
                uint32_t a[4], b0[4], b1[4];
                ldsm4(a,  qB + (wm * 16 + lr) * FPB + (ac + k16 * 16 + lk) * 2);
                ldsm4(b0, kB + (wn * 32 + lr) * FPB + (bc + k16 * 16 + lk) * 2);
                ldsm4(b1, kB + (wn * 32 + 16 + lr) * FPB + (bc + k16 * 16 + lk) * 2);
                mma16816(s[0], a, b0[0], b0[2]);
                mma16816(s[1], a, b0[1], b0[3]);
                mma16816(s[2], a, b1[0], b1[2]);
                mma16816(s[3], a, b1[1], b1[3]);
            }
        }
        // causal mask (diagonal block)
        if (kb == qb) {
            int rg0 = q0 + rowA;
            int cgb = (kb << 6) + wn * 32 + (lane & 3) * 2;
            #pragma unroll
            for (int n8 = 0; n8 < 4; n8++) {
                int cg = cgb + n8 * 8;
                if (cg     > rg0)     s[n8][0] = -1e30f;
                if (cg + 1 > rg0)     s[n8][1] = -1e30f;
                if (cg     > rg0 + 8) s[n8][2] = -1e30f;
                if (cg + 1 > rg0 + 8) s[n8][3] = -1e30f;
            }
        }
        // ---- partial row max -> smem ----
        float mx0 = -1e30f, mx1 = -1e30f;
        #pragma unroll
        for (int n8 = 0; n8 < 4; n8++) {
            mx0 = fmaxf(mx0, fmaxf(s[n8][0], s[n8][1]));
            mx1 = fmaxf(mx1, fmaxf(s[n8][2], s[n8][3]));
        }
        mx0 = fmaxf(mx0, __shfl_xor_sync(0xffffffffu, mx0, 1));
        mx0 = fmaxf(mx0, __shfl_xor_sync(0xffffffffu, mx0, 2));
        mx1 = fmaxf(mx1, __shfl_xor_sync(0xffffffffu, mx1, 1));
        mx1 = fmaxf(mx1, __shfl_xor_sync(0xffffffffu, mx1, 2));
        if ((lane & 3) == 0) {
            pmaxS[wn * 64 + rowA]     = mx0;
            pmaxS[wn * 64 + rowA + 8] = mx1;
        }
        __syncthreads();
        float mn0 = fmaxf(m0r, fmaxf(pmaxS[rowA],     pmaxS[64 + rowA]));
        float mn1 = fmaxf(m1r, fmaxf(pmaxS[rowA + 8], pmaxS[64 + rowA + 8]));
        float al0 = exp2f(m0r - mn0), al1 = exp2f(m1r - mn1);
        m0r = mn0; m1r = mn1;
        // exp (base-2), split P to smem, partial sums
        float ps0 = 0.f, ps1 = 0.f;
        #pragma unroll
        for (int n8 = 0; n8 < 4; n8++) {
            float e00 = exp2f(s[n8][0] - mn0);
            float e01 = exp2f(s[n8][1] - mn0);
            float e10 = exp2f(s[n8][2] - mn1);
            float e11 = exp2f(s[n8][3] - mn1);
            ps0 += e00 + e01;
            ps1 += e10 + e11;
            int col = wn * 32 + n8 * 8 + (lane & 3) * 2;
            uint32_t h0, lo0, h1, lo1;
            pack_split2(e00, e01, h0, lo0);
            pack_split2(e10, e11, h1, lo1);
            *(uint32_t*)(sm + FL_PH + rowA * PPB + col * 2)       = h0;
            *(uint32_t*)(sm + FL_PL + rowA * PPB + col * 2)       = lo0;
            *(uint32_t*)(sm + FL_PH + (rowA + 8) * PPB + col * 2) = h1;
            *(uint32_t*)(sm + FL_PL + (rowA + 8) * PPB + col * 2) = lo1;
        }
        ps0 += __shfl_xor_sync(0xffffffffu, ps0, 1);
        ps0 += __shfl_xor_sync(0xffffffffu, ps0, 2);
        ps1 += __shfl_xor_sync(0xffffffffu, ps1, 1);
        ps1 += __shfl_xor_sync(0xffffffffu, ps1, 2);
        if ((lane & 3) == 0) {
            lsumS[wn * 64 + rowA]     = ps0;
            lsumS[wn * 64 + rowA + 8] = ps1;
        }
        // rescale O (registers only)
        #pragma unroll
        for (int n8 = 0; n8 < 8; n8++) {
            o[n8][0] *= al0; o[n8][1] *= al0;
            o[n8][2] *= al1; o[n8][3] *= al1;
        }
        l0r *= al0; l1r *= al1;
        __syncthreads();
        l0r += lsumS[rowA]     + lsumS[64 + rowA];
        l1r += lsumS[rowA + 8] + lsumS[64 + rowA + 8];

        // ---- O += P V, 3 groups ----
        #pragma unroll
        for (int g = 0; g < 3; g++) {
            uint32_t pB = sb + ((g == 2) ? FL_PL : FL_PH);
            int vc = (g == 1) ? 128 : 0;
            #pragma unroll
            for (int k16 = 0; k16 < 4; k16++) {
                uint32_t a[4];
                ldsm4(a, pB + (wm * 16 + lr) * PPB + (k16 * 16 + lk) * 2);
                #pragma unroll
                for (int t16 = 0; t16 < 4; t16++) {
                    uint32_t bt[4];
                    ldsm4t(bt, vB + (k16 * 16 + lr) * FPB + (vc + wn * 64 + t16 * 16 + lk) * 2);
                    mma16816(o[t16 * 2],     a, bt[0], bt[1]);
                    mma16816(o[t16 * 2 + 1], a, bt[2], bt[3]);
                }
            }
        }
    }

    // epilogue: normalize, split, store [B,T,2048]
    float inv0 = 1.f / l0r, inv1 = 1.f / l1r;
    int b = bh >> 3, h = bh & 7;
    int t0 = q0 + rowA;
    #pragma unroll
    for (int n8 = 0; n8 < 8; n8++) {
        int d = wn * 64 + n8 * 8 + (lane & 3) * 2;
        size_t base0 = (size_t)(b * TT + t0) * 2048 + h * 128 + d;
        size_t base1 = base0 + 8 * 2048;
        uint32_t hp, lp;
        pack_split2(o[n8][0] * inv0, o[n8][1] * inv0, hp, lp);
        *(uint32_t*)&A2out[base0]        = hp;
        *(uint32_t*)&A2out[base0 + 1024] = lp;
        pack_split2(o[n8][2] * inv1, o[n8][3] * inv1, hp, lp);
        *(uint32_t*)&A2out[base1]        = hp;
        *(uint32_t*)&A2out[base1 + 1024] = lp;
    }
}

// ============================================================
// Launch
// ============================================================
extern "C" void kernel_launch(void* const* d_in, const int* in_sizes, int n_in,
                              void* d_out, int out_size)
{
    const float* x     = (const float*)d_in[0];
    const float* gamma = (const float*)d_in[1];
    const float* beta  = (const float*)d_in[2];
    const float* Wq    = (const float*)d_in[3];
    const float* Wk    = (const float*)d_in[4];
    const float* Wv    = (const float*)d_in[5];
    const float* Wo    = (const float*)d_in[6];
    float* out = (float*)d_out;

    __nv_bfloat16 *xn2, *w2, *q2, *k2, *v2, *attn2;
    cudaGetSymbolAddress((void**)&xn2,   g_xn2);
    cudaGetSymbolAddress((void**)&w2,    g_w2);
    cudaGetSymbolAddress((void**)&q2,    g_q2);
    cudaGetSymbolAddress((void**)&k2,    g_k2);
    cudaGetSymbolAddress((void**)&v2,    g_v2);
    cudaGetSymbolAddress((void**)&attn2, g_attn2);

    cudaFuncSetAttribute(gemm_mma_qkv, cudaFuncAttributeMaxDynamicSharedMemorySize, GEMM_SMEM);
    cudaFuncSetAttribute(gemm_mma_out, cudaFuncAttributeMaxDynamicSharedMemorySize, GEMM_SMEM);
    cudaFuncSetAttribute(flash_mma, cudaFuncAttributeMaxDynamicSharedMemorySize, FLASH_SMEM);

    ln_kernel<<<MM, 256>>>(x, gamma, beta, xn2);

    conv_split<<<1024, 256>>>(Wq, w2 + (size_t)0 * 1024 * 2048);
    conv_split<<<1024, 256>>>(Wk, w2 + (size_t)1 * 1024 * 2048);
    conv_split<<<1024, 256>>>(Wv, w2 + (size_t)2 * 1024 * 2048);
    conv_split<<<1024, 256>>>(Wo, w2 + (size_t)3 * 1024 * 2048);

    // scale*log2(e) folded into Q so softmax runs in base 2
    const float qscale = 0.08838834764831845f * 1.44269504088896341f;
    dim3 gg(HD / 128, MM / 128);   // (8, 64)
    gemm_mma_qkv<<<gg, 256, GEMM_SMEM>>>(xn2, w2 + (size_t)0 * 1024 * 2048, q2, qscale);
    gemm_mma_qkv<<<gg, 256, GEMM_SMEM>>>(xn2, w2 + (size_t)1 * 1024 * 2048, k2, 1.0f);
    gemm_mma_qkv<<<gg, 256, GEMM_SMEM>>>(xn2, w2 + (size_t)2 * 1024 * 2048, v2, 1.0f);

    flash_mma<<<dim3(TT / 64, BB * NH), 256, FLASH_SMEM>>>(q2, k2, v2, attn2);

    gemm_mma_out<<<gg, 256, GEMM_SMEM>>>(attn2, w2 + (size_t)3 * 1024 * 2048, out, x);
}